// round 16
// baseline (speedup 1.0000x reference)
#include <cuda_runtime.h>
#include <cuda_fp16.h>
#include <cuda_bf16.h>
#include <math.h>

#define NN   8192
#define DIN  512
#define DOUT 256
#define BM   64
#define BN2  128
#define BK   32
#define NGEMM ((NN / BM) * (DOUT / BN2))     // 256 gemm blocks
#define SA   40                              // smem stride (halves)
#define MAXDEG 128
#define NSCAN NN                             // 1 row per scan block

// Device scratch
__device__ __half d_wT[(size_t)DOUT * DIN];   // W1^T fp16 (256 KB)
__device__ __half d_h16[(size_t)NN * DOUT];   // h fp16 (4 MB)
__device__ float  d_w1eff[DIN];               // W1 @ a1w
__device__ float  d_w2eff[DIN];               // W1 @ a2w
__device__ float  d_c[2];                     // b1.a1w + a1b, b1.a2w + a2b
__device__ float  d_g1[NN];
__device__ float  d_g2[NN];
__device__ int2   d_pe[(size_t)NN * MAXDEG];  // (idx, p/S) per edge (8 MB)
__device__ int    d_cnt[NN];

__device__ __forceinline__ float fast_elu(float v) {
    return v > 0.f ? v : (__expf(v) - 1.f);
}
__device__ __forceinline__ unsigned h2_bits(__half2 h) {
    return *reinterpret_cast<unsigned*>(&h);
}

#define LDM_X4(r, addr)                                                     \
    asm volatile("ldmatrix.sync.aligned.m8n8.x4.shared.b16 "                \
                 "{%0,%1,%2,%3}, [%4];"                                     \
                 : "=r"((r)[0]), "=r"((r)[1]), "=r"((r)[2]), "=r"((r)[3])   \
                 : "r"(addr))

#define MMA16816(d, a, b0, b1)                                              \
    asm volatile("mma.sync.aligned.m16n8k16.row.col.f32.f16.f16.f32 "       \
                 "{%0,%1,%2,%3}, {%4,%5,%6,%7}, {%8,%9}, {%0,%1,%2,%3};"    \
                 : "+f"((d)[0]), "+f"((d)[1]), "+f"((d)[2]), "+f"((d)[3])   \
                 : "r"((a)[0]), "r"((a)[1]), "r"((a)[2]), "r"((a)[3]),      \
                   "r"(b0), "r"(b1))

// ---------------------------------------------------------------------------
// Kernel 0: prep.
//  blocks [0,128): d_wT = fp16(W1^T) smem transpose.
//  block 128: d_w1eff[k] = W1[k,:].a1w; warp0 also d_c[0] = b1.a1w + a1b.
//  block 129: same for a2w / d_c[1].
// ---------------------------------------------------------------------------
__global__ __launch_bounds__(256) void prep_w(
    const float* __restrict__ W, const float* __restrict__ b1,
    const float* __restrict__ a1w, const float* __restrict__ a1b,
    const float* __restrict__ a2w, const float* __restrict__ a2b)
{
    const int tid = threadIdx.x;
    const int lane = tid & 31;
    if (blockIdx.x < 128) {
        __shared__ float t[32][33];
        const int tr = blockIdx.x >> 3, tc = blockIdx.x & 7;
        const int tx = tid & 31, ty8 = tid >> 5;
        #pragma unroll
        for (int r = 0; r < 4; ++r) {
            int j = ty8 * 4 + r;
            t[j][tx] = W[(size_t)(tr * 32 + j) * DOUT + tc * 32 + tx];
        }
        __syncthreads();
        #pragma unroll
        for (int r = 0; r < 4; ++r) {
            int a = ty8 * 4 + r;
            d_wT[(size_t)(tc * 32 + a) * DIN + tr * 32 + tx] =
                __float2half_rn(t[tx][a]);
        }
    } else {
        const float* aw  = (blockIdx.x == 128) ? a1w : a2w;
        float* weff      = (blockIdx.x == 128) ? d_w1eff : d_w2eff;
        const int w = tid >> 5;
        for (int k = w; k < DIN; k += 8) {
            float s = 0.f;
            #pragma unroll
            for (int q = 0; q < 2; ++q) {
                float4 wv = *(const float4*)(W + (size_t)k * DOUT + lane * 8 + q * 4);
                float4 av = *(const float4*)(aw + lane * 8 + q * 4);
                s += wv.x * av.x + wv.y * av.y + wv.z * av.z + wv.w * av.w;
            }
            #pragma unroll
            for (int o = 16; o; o >>= 1) s += __shfl_xor_sync(0xffffffffu, s, o);
            if (lane == 0) weff[k] = s;
        }
        if (w == 0) {   // c = b1.aw + ab
            float s = 0.f;
            #pragma unroll
            for (int q = 0; q < 2; ++q) {
                float4 bv = *(const float4*)(b1 + lane * 8 + q * 4);
                float4 av = *(const float4*)(aw + lane * 8 + q * 4);
                s += bv.x * av.x + bv.y * av.y + bv.z * av.z + bv.w * av.w;
            }
            #pragma unroll
            for (int o = 16; o; o >>= 1) s += __shfl_xor_sync(0xffffffffu, s, o);
            if (lane == 0)
                d_c[blockIdx.x - 128] = s + ((blockIdx.x == 128) ? a1b[0] : a2b[0]);
        }
    }
}

// ---------------------------------------------------------------------------
// Kernel 1: g1[i] = elu(x[i]).w1eff + c1 ; g2 likewise. Warp per row, fp32.
// ---------------------------------------------------------------------------
__global__ __launch_bounds__(256) void g_kernel(const float* __restrict__ x)
{
    const int lane = threadIdx.x & 31;
    const int i = blockIdx.x * 8 + (threadIdx.x >> 5);
    const float4* xp = (const float4*)(x + (size_t)i * DIN);
    const float4* w1p = (const float4*)d_w1eff;
    const float4* w2p = (const float4*)d_w2eff;

    float d1 = 0.f, d2 = 0.f;
    #pragma unroll
    for (int q = 0; q < 4; ++q) {
        int j = lane + q * 32;
        float4 xv = xp[j];
        xv.x = fast_elu(xv.x); xv.y = fast_elu(xv.y);
        xv.z = fast_elu(xv.z); xv.w = fast_elu(xv.w);
        float4 w1 = w1p[j], w2 = w2p[j];
        d1 += xv.x * w1.x + xv.y * w1.y + xv.z * w1.z + xv.w * w1.w;
        d2 += xv.x * w2.x + xv.y * w2.y + xv.z * w2.z + xv.w * w2.w;
    }
    #pragma unroll
    for (int o = 16; o; o >>= 1) {
        d1 += __shfl_xor_sync(0xffffffffu, d1, o);
        d2 += __shfl_xor_sync(0xffffffffu, d2, o);
    }
    if (lane == 0) {
        d_g1[i] = d1 + d_c[0];
        d_g2[i] = d2 + d_c[1];
    }
}

// ---------------------------------------------------------------------------
// Kernel A: heterogeneous.
//  blocks [0, 256):  fp16 tensor GEMM h = elu(x) @ W1 + b1 (plain epilogue).
//  blocks [256, 256+8192): scan + in-block softmax; writes (idx, p/S).
// GEMM and scan are fully independent (g already computed).
// ---------------------------------------------------------------------------
__global__ __launch_bounds__(256) void gemm_scan(
    const float* __restrict__ x, const float* __restrict__ b,
    const float* __restrict__ adj)
{
    __shared__ __half Asm[2][BM * SA];
    __shared__ __half Bsm[2][BN2 * SA];
    __shared__ int   s_idx[MAXDEG];
    __shared__ float s_p[MAXDEG];
    __shared__ int   s_cnt;
    __shared__ float s_red[8];
    __shared__ float s_m, s_S;

    const int tid = threadIdx.x;
    const int lane = tid & 31;

    if (blockIdx.x < NGEMM) {
        // ========================= GEMM =========================
        const int warp = tid >> 5;
        const int wm = warp >> 2, wn = warp & 3;
        const int gq = lane >> 2, tg = lane & 3;
        const int rowBase = (blockIdx.x >> 1) * BM;
        const int colBase = (blockIdx.x & 1) * BN2;

        const int a_m = tid >> 2, a_kq = (tid & 3) * 8;
        const float* aptr = x + (size_t)(rowBase + a_m) * DIN + a_kq;
        const int b_n = tid >> 2, b_kq = (tid & 3) * 8;
        const __half* bptr0 = d_wT + (size_t)(colBase + b_n) * DIN + b_kq;
        const __half* bptr1 = bptr0 + (size_t)64 * DIN;

        const unsigned aRow = (wm * 32 + (lane & 15)) * (SA * 2) + ((lane >> 4) & 1) * 16;
        const unsigned bRow = (wn * 32 + (lane & 7) + ((lane >> 4) & 1) * 8) * (SA * 2)
                              + ((lane >> 3) & 1) * 16;

        float acc[2][4][4] = {};
        float4 aF0, aF1;
        uint4 bR0, bR1;

        auto ldg_stage = [&](int k0) {
            aF0 = *(const float4*)(aptr + k0);
            aF1 = *(const float4*)(aptr + k0 + 4);
            bR0 = *(const uint4*)(bptr0 + k0);
            bR1 = *(const uint4*)(bptr1 + k0);
        };
        auto sts_stage = [&](int buf) {
            __half2 h0 = __floats2half2_rn(fast_elu(aF0.x), fast_elu(aF0.y));
            __half2 h1 = __floats2half2_rn(fast_elu(aF0.z), fast_elu(aF0.w));
            __half2 h2 = __floats2half2_rn(fast_elu(aF1.x), fast_elu(aF1.y));
            __half2 h3 = __floats2half2_rn(fast_elu(aF1.z), fast_elu(aF1.w));
            uint4 u;
            u.x = h2_bits(h0); u.y = h2_bits(h1);
            u.z = h2_bits(h2); u.w = h2_bits(h3);
            *(uint4*)&Asm[buf][a_m * SA + a_kq] = u;
            *(uint4*)&Bsm[buf][b_n * SA + b_kq] = bR0;
            *(uint4*)&Bsm[buf][(b_n + 64) * SA + b_kq] = bR1;
        };
        auto compute = [&](int buf) {
            unsigned aBase = (unsigned)__cvta_generic_to_shared(&Asm[buf][0]);
            unsigned bBase = (unsigned)__cvta_generic_to_shared(&Bsm[buf][0]);
            #pragma unroll
            for (int c = 0; c < 2; ++c) {
                unsigned afr[2][4], bfr[2][4];
                #pragma unroll
                for (int mt = 0; mt < 2; ++mt)
                    LDM_X4(afr[mt], aBase + aRow + mt * 16 * SA * 2 + c * 32);
                #pragma unroll
                for (int nh = 0; nh < 2; ++nh)
                    LDM_X4(bfr[nh], bBase + bRow + nh * 16 * SA * 2 + c * 32);
                #pragma unroll
                for (int mt = 0; mt < 2; ++mt)
                    #pragma unroll
                    for (int nt = 0; nt < 4; ++nt)
                        MMA16816(acc[mt][nt], afr[mt],
                                 bfr[nt >> 1][(nt & 1) * 2],
                                 bfr[nt >> 1][(nt & 1) * 2 + 1]);
            }
        };

        ldg_stage(0);
        sts_stage(0);
        __syncthreads();
        #pragma unroll 1
        for (int it = 0; it < DIN / BK; ++it) {
            if (it + 1 < DIN / BK) ldg_stage((it + 1) * BK);
            compute(it & 1);
            if (it + 1 < DIN / BK) {
                sts_stage((it + 1) & 1);
                __syncthreads();
            }
        }

        // Epilogue: + bias, write fp16 h.
        #pragma unroll
        for (int mt = 0; mt < 2; ++mt) {
            int r0 = rowBase + wm * 32 + mt * 16 + gq;
            #pragma unroll
            for (int nt = 0; nt < 4; ++nt) {
                int col = colBase + wn * 32 + nt * 8 + tg * 2;
                float2 bias = *(const float2*)(b + col);
                *(__half2*)&d_h16[(size_t)r0 * DOUT + col] =
                    __floats2half2_rn(acc[mt][nt][0] + bias.x,
                                      acc[mt][nt][1] + bias.y);
                *(__half2*)&d_h16[(size_t)(r0 + 8) * DOUT + col] =
                    __floats2half2_rn(acc[mt][nt][2] + bias.x,
                                      acc[mt][nt][3] + bias.y);
            }
        }
    } else {
        // ============ SCAN + SOFTMAX (1 row per block) ============
        const int row = blockIdx.x - NGEMM;
        if (tid == 0) s_cnt = 0;
        __syncthreads();

        const float4* rowp = (const float4*)(adj + (size_t)row * NN);
        const unsigned below = (1u << lane) - 1u;
        float4 v[8];
        #pragma unroll
        for (int it = 0; it < 8; ++it)            // front-batched MLP=8
            v[it] = __ldcs(rowp + it * 256 + tid);
        #pragma unroll
        for (int it = 0; it < 8; ++it) {
            float4 a = v[it];
            unsigned m0 = __ballot_sync(0xffffffffu, a.x > 0.f);
            unsigned m1 = __ballot_sync(0xffffffffu, a.y > 0.f);
            unsigned m2 = __ballot_sync(0xffffffffu, a.z > 0.f);
            unsigned m3 = __ballot_sync(0xffffffffu, a.w > 0.f);
            int tot = __popc(m0) + __popc(m1) + __popc(m2) + __popc(m3);
            int base = 0;
            if (lane == 0) base = atomicAdd(&s_cnt, tot);
            base = __shfl_sync(0xffffffffu, base, 0);
            int o = base + __popc(m0 & below) + __popc(m1 & below)
                         + __popc(m2 & below) + __popc(m3 & below);
            int col = (it * 256 + tid) * 4;
            if (a.x > 0.f) { if (o < MAXDEG) s_idx[o] = col;     o++; }
            if (a.y > 0.f) { if (o < MAXDEG) s_idx[o] = col + 1; o++; }
            if (a.z > 0.f) { if (o < MAXDEG) s_idx[o] = col + 2; o++; }
            if (a.w > 0.f) { if (o < MAXDEG) s_idx[o] = col + 3; o++; }
        }
        __syncthreads();
        const int cnt = min(s_cnt, MAXDEG);

        // in-block softmax over <=128 edges (one per thread)
        const float g2i = d_g2[row];
        float e = -INFINITY;
        if (tid < cnt) {
            float sc = g2i + d_g1[s_idx[tid]];
            e = sc > 0.f ? sc : 0.2f * sc;        // leaky_relu(0.2)
        }
        float m = e;
        #pragma unroll
        for (int o = 16; o; o >>= 1) m = fmaxf(m, __shfl_xor_sync(0xffffffffu, m, o));
        if (lane == 0) s_red[tid >> 5] = m;
        __syncthreads();
        if (tid < 8) {
            float xx = s_red[tid];
            #pragma unroll
            for (int o = 4; o; o >>= 1) xx = fmaxf(xx, __shfl_xor_sync(0xffu, xx, o));
            if (tid == 0) s_m = xx;
        }
        __syncthreads();

        float p = 0.f;
        if (tid < cnt) { p = __expf(e - s_m); s_p[tid] = p; }
        float s = p;
        #pragma unroll
        for (int o = 16; o; o >>= 1) s += __shfl_xor_sync(0xffffffffu, s, o);
        __syncthreads();
        if (lane == 0) s_red[tid >> 5] = s;
        __syncthreads();
        if (tid < 8) {
            float xx = s_red[tid];
            #pragma unroll
            for (int o = 4; o; o >>= 1) xx += __shfl_xor_sync(0xffu, xx, o);
            if (tid == 0) s_S = xx;
        }
        __syncthreads();

        if (tid < cnt)
            d_pe[(size_t)row * MAXDEG + tid] =
                make_int2(s_idx[tid], __float_as_int(s_p[tid] / s_S));
        if (tid == 0) d_cnt[row] = cnt;
    }
}

// ---------------------------------------------------------------------------
// Kernel B: warp-per-row aggregation. Pure gather: p already normalized.
// ---------------------------------------------------------------------------
__global__ __launch_bounds__(256) void agg(float* __restrict__ out)
{
    const int lane = threadIdx.x & 31;
    const int i = blockIdx.x * 8 + (threadIdx.x >> 5);
    const int cnt = d_cnt[i];

    int   idx[4];
    float pp[4];
    #pragma unroll
    for (int q = 0; q < 4; ++q) {
        int t = lane + q * 32;
        if (t < cnt) {
            int2 e = d_pe[(size_t)i * MAXDEG + t];   // coalesced 8B
            idx[q] = e.x;
            pp[q]  = __int_as_float(e.y);
        } else { idx[q] = 0; pp[q] = 0.f; }
    }

    float acc[8] = {};
    if (cnt > 0) {
        #pragma unroll
        for (int q = 0; q < 4; ++q) {
            int base = q * 32;
            if (base >= cnt) break;
            int lim = min(cnt - base, 32);
            int t = 0;
            for (; t + 4 <= lim; t += 4) {            // 4 gathers in flight
                float p0 = __shfl_sync(0xffffffffu, pp[q], t);
                float p1 = __shfl_sync(0xffffffffu, pp[q], t + 1);
                float p2 = __shfl_sync(0xffffffffu, pp[q], t + 2);
                float p3 = __shfl_sync(0xffffffffu, pp[q], t + 3);
                int j0 = __shfl_sync(0xffffffffu, idx[q], t);
                int j1 = __shfl_sync(0xffffffffu, idx[q], t + 1);
                int j2 = __shfl_sync(0xffffffffu, idx[q], t + 2);
                int j3 = __shfl_sync(0xffffffffu, idx[q], t + 3);
                uint4 h0 = *(const uint4*)(d_h16 + (size_t)j0 * DOUT + lane * 8);
                uint4 h1 = *(const uint4*)(d_h16 + (size_t)j1 * DOUT + lane * 8);
                uint4 h2 = *(const uint4*)(d_h16 + (size_t)j2 * DOUT + lane * 8);
                uint4 h3 = *(const uint4*)(d_h16 + (size_t)j3 * DOUT + lane * 8);
                const __half2* q0 = (const __half2*)&h0;
                const __half2* q1 = (const __half2*)&h1;
                const __half2* q2 = (const __half2*)&h2;
                const __half2* q3 = (const __half2*)&h3;
                #pragma unroll
                for (int k = 0; k < 4; ++k) {
                    float2 f0 = __half22float2(q0[k]);
                    float2 f1 = __half22float2(q1[k]);
                    float2 f2 = __half22float2(q2[k]);
                    float2 f3 = __half22float2(q3[k]);
                    acc[2*k]   += p0 * f0.x + p1 * f1.x + p2 * f2.x + p3 * f3.x;
                    acc[2*k+1] += p0 * f0.y + p1 * f1.y + p2 * f2.y + p3 * f3.y;
                }
            }
            for (; t < lim; ++t) {
                float p0 = __shfl_sync(0xffffffffu, pp[q], t);
                int j0 = __shfl_sync(0xffffffffu, idx[q], t);
                uint4 h0 = *(const uint4*)(d_h16 + (size_t)j0 * DOUT + lane * 8);
                const __half2* q0 = (const __half2*)&h0;
                #pragma unroll
                for (int k = 0; k < 4; ++k) {
                    float2 f0 = __half22float2(q0[k]);
                    acc[2*k]   += p0 * f0.x;
                    acc[2*k+1] += p0 * f0.y;
                }
            }
        }
    } else {
        // zero-degree row -> uniform softmax -> mean of h
        for (int j = 0; j < NN; ++j) {
            uint4 h0 = *(const uint4*)(d_h16 + (size_t)j * DOUT + lane * 8);
            const __half2* q0 = (const __half2*)&h0;
            #pragma unroll
            for (int k = 0; k < 4; ++k) {
                float2 f0 = __half22float2(q0[k]);
                acc[2*k] += f0.x; acc[2*k+1] += f0.y;
            }
        }
        #pragma unroll
        for (int k = 0; k < 8; ++k) acc[k] *= (1.f / NN);
    }

    float4 r0 = {acc[0], acc[1], acc[2], acc[3]};
    float4 r1 = {acc[4], acc[5], acc[6], acc[7]};
    *(float4*)(out + (size_t)i * DOUT + lane * 8)     = r0;
    *(float4*)(out + (size_t)i * DOUT + lane * 8 + 4) = r1;
}

// ---------------------------------------------------------------------------
extern "C" void kernel_launch(void* const* d_in, const int* in_sizes, int n_in,
                              void* d_out, int out_size)
{
    const float* x   = (const float*)d_in[0];
    const float* adj = (const float*)d_in[1];
    const float* W1  = (const float*)d_in[2];
    const float* b1  = (const float*)d_in[3];
    const float* a1w = (const float*)d_in[4];
    const float* a1b = (const float*)d_in[5];
    const float* a2w = (const float*)d_in[6];
    const float* a2b = (const float*)d_in[7];
    float* out = (float*)d_out;

    prep_w<<<130, 256>>>(W1, b1, a1w, a1b, a2w, a2b);
    g_kernel<<<NN / 8, 256>>>(x);
    gemm_scan<<<NGEMM + NSCAN, 256>>>(x, b1, adj);
    agg<<<NN / 8, 256>>>(out);
}